// round 1
// baseline (speedup 1.0000x reference)
#include <cuda_runtime.h>
#include <cuda_bf16.h>

// Problem constants
#define B_  4
#define L_  2048
#define H_  1024
#define NH_ 16
#define DK_ 64
#define ROWS_ (B_ * L_)          // 8192
#define HEADS_ (B_ * NH_)        // 64
#define NROWS_ (HEADS_ * L_)     // 131072

// Scratch (device globals: allocation-free rule)
__device__ float g_Q[HEADS_ * L_ * DK_];   // (head, l, dk)
__device__ float g_K[HEADS_ * L_ * DK_];
__device__ float g_V[HEADS_ * L_ * DK_];
__device__ float g_S[(size_t)HEADS_ * L_ * L_];  // 1 GiB scores
__device__ float g_m[NROWS_];
__device__ float g_linv[NROWS_];
__device__ float g_cs[HEADS_ * L_];        // per-head column sums of attn
__device__ float g_ctxmean[B_ * H_];       // mean over L of context

// ---------------------------------------------------------------------------
// Kernel 1: Y = x @ W^T + b, scaled by alpha, stored as (b, nh, l, dk)
// M=8192, N=1024, K=1024. BM=BN=128, BK=16, 256 threads, 8x8 per thread.
// ---------------------------------------------------------------------------
__global__ __launch_bounds__(256)
void gemm_qkv(const float* __restrict__ A, const float* __restrict__ W,
              const float* __restrict__ bias, float* __restrict__ out,
              float alpha)
{
    __shared__ float As[16][128];
    __shared__ float Ws[16][128];

    const int tid = threadIdx.x;
    const int tx = tid & 15;
    const int ty = tid >> 4;
    const int rowBase = blockIdx.y * 128;
    const int colBase = blockIdx.x * 128;

    float acc[8][8];
#pragma unroll
    for (int i = 0; i < 8; i++)
#pragma unroll
        for (int j = 0; j < 8; j++) acc[i][j] = 0.f;

    for (int k0 = 0; k0 < H_; k0 += 16) {
#pragma unroll
        for (int i = 0; i < 2; i++) {
            int idx = tid + i * 256;          // 0..511 float4 slots
            int m  = idx >> 2;                // 0..127
            int kk = (idx & 3) << 2;          // 0,4,8,12
            float4 v = *(const float4*)&A[(size_t)(rowBase + m) * H_ + k0 + kk];
            As[kk + 0][m] = v.x; As[kk + 1][m] = v.y;
            As[kk + 2][m] = v.z; As[kk + 3][m] = v.w;
        }
#pragma unroll
        for (int i = 0; i < 2; i++) {
            int idx = tid + i * 256;
            int n  = idx >> 2;
            int kk = (idx & 3) << 2;
            float4 v = *(const float4*)&W[(size_t)(colBase + n) * H_ + k0 + kk];
            Ws[kk + 0][n] = v.x; Ws[kk + 1][n] = v.y;
            Ws[kk + 2][n] = v.z; Ws[kk + 3][n] = v.w;
        }
        __syncthreads();

#pragma unroll
        for (int k = 0; k < 16; k++) {
            float4 a0 = *(const float4*)&As[k][ty * 8];
            float4 a1 = *(const float4*)&As[k][ty * 8 + 4];
            float4 b0 = *(const float4*)&Ws[k][tx * 8];
            float4 b1 = *(const float4*)&Ws[k][tx * 8 + 4];
            float av[8] = {a0.x, a0.y, a0.z, a0.w, a1.x, a1.y, a1.z, a1.w};
            float bv[8] = {b0.x, b0.y, b0.z, b0.w, b1.x, b1.y, b1.z, b1.w};
#pragma unroll
            for (int i = 0; i < 8; i++)
#pragma unroll
                for (int j = 0; j < 8; j++) acc[i][j] += av[i] * bv[j];
        }
        __syncthreads();
    }

#pragma unroll
    for (int i = 0; i < 8; i++) {
        int r = rowBase + ty * 8 + i;
        int bb = r >> 11;          // / L_
        int l  = r & (L_ - 1);
#pragma unroll
        for (int j = 0; j < 8; j++) {
            int c  = colBase + tx * 8 + j;
            int nh = c >> 6;
            int dk = c & 63;
            float val = (acc[i][j] + bias[c]) * alpha;
            out[((size_t)((bb * NH_ + nh) * L_ + l)) * DK_ + dk] = val;
        }
    }
}

// ---------------------------------------------------------------------------
// Kernel 2: S[head] = Q[head] @ K[head]^T   (2048 x 2048, K=64)
// BM=BN=64, 256 threads, 4x4 per thread. grid (32, 32, 64)
// ---------------------------------------------------------------------------
__global__ __launch_bounds__(256)
void scores_kernel()
{
    __shared__ float Qs[64][68];   // [dk][m], padded
    __shared__ float Ks[64][68];   // [dk][n]

    const int tid = threadIdx.x;
    const int tx = tid & 15;
    const int ty = tid >> 4;
    const int kBase = blockIdx.x * 64;
    const int qBase = blockIdx.y * 64;
    const int head  = blockIdx.z;

    const float* Qh = g_Q + (size_t)head * L_ * DK_;
    const float* Kh = g_K + (size_t)head * L_ * DK_;

#pragma unroll
    for (int i = 0; i < 4; i++) {
        int idx = tid + i * 256;       // 0..1023 float4 slots
        int m   = idx >> 4;            // 0..63
        int dk4 = (idx & 15) << 2;     // 0..60
        float4 q = *(const float4*)&Qh[(size_t)(qBase + m) * DK_ + dk4];
        Qs[dk4 + 0][m] = q.x; Qs[dk4 + 1][m] = q.y;
        Qs[dk4 + 2][m] = q.z; Qs[dk4 + 3][m] = q.w;
        float4 k = *(const float4*)&Kh[(size_t)(kBase + m) * DK_ + dk4];
        Ks[dk4 + 0][m] = k.x; Ks[dk4 + 1][m] = k.y;
        Ks[dk4 + 2][m] = k.z; Ks[dk4 + 3][m] = k.w;
    }
    __syncthreads();

    float acc[4][4];
#pragma unroll
    for (int i = 0; i < 4; i++)
#pragma unroll
        for (int j = 0; j < 4; j++) acc[i][j] = 0.f;

#pragma unroll
    for (int k = 0; k < 64; k++) {
        float4 a = *(const float4*)&Qs[k][ty * 4];
        float4 b = *(const float4*)&Ks[k][tx * 4];
        float av[4] = {a.x, a.y, a.z, a.w};
        float bv[4] = {b.x, b.y, b.z, b.w};
#pragma unroll
        for (int i = 0; i < 4; i++)
#pragma unroll
            for (int j = 0; j < 4; j++) acc[i][j] += av[i] * bv[j];
    }

    float* Sh = g_S + (size_t)head * L_ * L_;
#pragma unroll
    for (int i = 0; i < 4; i++) {
        float4 v = make_float4(acc[i][0], acc[i][1], acc[i][2], acc[i][3]);
        *(float4*)&Sh[(size_t)(qBase + ty * 4 + i) * L_ + kBase + tx * 4] = v;
    }
}

// ---------------------------------------------------------------------------
// Kernel 3: per-row max and 1/sum(exp(s-m)). One warp per row.
// ---------------------------------------------------------------------------
__global__ __launch_bounds__(256)
void stats_kernel()
{
    const int warp = threadIdx.x >> 5;
    const int lane = threadIdx.x & 31;
    const int row  = blockIdx.x * 8 + warp;   // 0..131071
    const float* p = g_S + (size_t)row * L_;

    float v[64];
    float m = -1e30f;
#pragma unroll
    for (int i = 0; i < 64; i++) {
        v[i] = p[lane + i * 32];
        m = fmaxf(m, v[i]);
    }
#pragma unroll
    for (int off = 16; off > 0; off >>= 1)
        m = fmaxf(m, __shfl_xor_sync(0xFFFFFFFFu, m, off));

    float s = 0.f;
#pragma unroll
    for (int i = 0; i < 64; i++) s += __expf(v[i] - m);
#pragma unroll
    for (int off = 16; off > 0; off >>= 1)
        s += __shfl_xor_sync(0xFFFFFFFFu, s, off);

    if (lane == 0) {
        g_m[row] = m;
        g_linv[row] = 1.f / s;
    }
}

// ---------------------------------------------------------------------------
// Kernel 4: zero cs
// ---------------------------------------------------------------------------
__global__ void zero_cs()
{
    int i = blockIdx.x * blockDim.x + threadIdx.x;
    if (i < HEADS_ * L_) g_cs[i] = 0.f;
}

// ---------------------------------------------------------------------------
// Kernel 5: column sums of attn: cs[head][k] += sum_q exp(S-m)*linv
// grid (8 kchunks, 8 qchunks, 64 heads), 256 threads (one col each)
// ---------------------------------------------------------------------------
__global__ __launch_bounds__(256)
void colsum_kernel()
{
    const int col  = blockIdx.x * 256 + threadIdx.x;
    const int q0   = blockIdx.y * 256;
    const int head = blockIdx.z;

    const float* Sh = g_S + (size_t)head * L_ * L_;
    const float* mp = g_m + (size_t)head * L_;
    const float* lp = g_linv + (size_t)head * L_;

    float acc = 0.f;
#pragma unroll 4
    for (int q = q0; q < q0 + 256; q++) {
        float s = Sh[(size_t)q * L_ + col];
        acc += __expf(s - mp[q]) * lp[q];
    }
    atomicAdd(&g_cs[head * L_ + col], acc);
}

// ---------------------------------------------------------------------------
// Kernel 6: ctxmean[b, nh*64+dk] = (1/L) * sum_k cs[head,k] * V[head,k,dk]
// grid 64 (head), 256 threads (dk x 4 k-slices)
// ---------------------------------------------------------------------------
__global__ __launch_bounds__(256)
void ctxmean_kernel()
{
    __shared__ float sm[4][64];
    const int head = blockIdx.x;
    const int dk = threadIdx.x & 63;
    const int ks = threadIdx.x >> 6;

    const float* Vh = g_V + (size_t)head * L_ * DK_;
    const float* cs = g_cs + head * L_;

    float acc = 0.f;
    for (int k = ks; k < L_; k += 4)
        acc += cs[k] * Vh[(size_t)k * DK_ + dk];
    sm[ks][dk] = acc;
    __syncthreads();
    if (threadIdx.x < 64) {
        float t = sm[0][dk] + sm[1][dk] + sm[2][dk] + sm[3][dk];
        int b  = head >> 4;
        int nh = head & 15;
        g_ctxmean[b * H_ + nh * DK_ + dk] = t * (1.f / (float)L_);
    }
}

// ---------------------------------------------------------------------------
// Kernel 7: pooled[b,o] = ctxmean[b,:] . Wo[o,:] + bo[o]   (one warp per out)
// grid 512 blocks x 256 threads (8 warps) = 4096 warps
// ---------------------------------------------------------------------------
__global__ __launch_bounds__(256)
void pooled_kernel(const float* __restrict__ Wo, const float* __restrict__ bo,
                   float* __restrict__ out)
{
    const int warp = threadIdx.x >> 5;
    const int lane = threadIdx.x & 31;
    const int idx = blockIdx.x * 8 + warp;   // 0..4095
    const int b = idx >> 10;
    const int o = idx & 1023;

    const float* cm = g_ctxmean + b * H_;
    const float* wr = Wo + (size_t)o * H_;
    float acc = 0.f;
#pragma unroll
    for (int h = lane; h < H_; h += 32) acc += cm[h] * wr[h];
#pragma unroll
    for (int off = 16; off > 0; off >>= 1)
        acc += __shfl_xor_sync(0xFFFFFFFFu, acc, off);
    if (lane == 0) out[idx] = acc + bo[o];
}

// ---------------------------------------------------------------------------
// Kernel 8: weights[b,k] = (1/(NH*L)) sum_nh cs[(b*16+nh), k]
// ---------------------------------------------------------------------------
__global__ void weights_kernel(float* __restrict__ out)
{
    int i = blockIdx.x * blockDim.x + threadIdx.x;  // 0..8191
    if (i >= B_ * L_) return;
    int b = i >> 11;
    int k = i & (L_ - 1);
    float s = 0.f;
#pragma unroll
    for (int nh = 0; nh < NH_; nh++)
        s += g_cs[(b * NH_ + nh) * L_ + k];
    out[B_ * H_ + i] = s * (1.f / (float)(NH_ * L_));
}

// ---------------------------------------------------------------------------
extern "C" void kernel_launch(void* const* d_in, const int* in_sizes, int n_in,
                              void* d_out, int out_size)
{
    const float* x  = (const float*)d_in[0];
    const float* Wq = (const float*)d_in[1];
    const float* bq = (const float*)d_in[2];
    const float* Wk = (const float*)d_in[3];
    const float* bk = (const float*)d_in[4];
    const float* Wv = (const float*)d_in[5];
    const float* bv = (const float*)d_in[6];
    const float* Wo = (const float*)d_in[7];
    const float* bo = (const float*)d_in[8];
    float* out = (float*)d_out;

    float* dQ; cudaGetSymbolAddress((void**)&dQ, g_Q);
    float* dK; cudaGetSymbolAddress((void**)&dK, g_K);
    float* dV; cudaGetSymbolAddress((void**)&dV, g_V);

    dim3 gG(H_ / 128, ROWS_ / 128);   // (8, 64)
    const float inv_sqrt_dk = 0.125f; // 1/sqrt(64)
    gemm_qkv<<<gG, 256>>>(x, Wq, bq, dQ, inv_sqrt_dk);
    gemm_qkv<<<gG, 256>>>(x, Wk, bk, dK, 1.0f);
    gemm_qkv<<<gG, 256>>>(x, Wv, bv, dV, 1.0f);

    scores_kernel<<<dim3(L_ / 64, L_ / 64, HEADS_), 256>>>();

    stats_kernel<<<NROWS_ / 8, 256>>>();

    zero_cs<<<(HEADS_ * L_ + 255) / 256, 256>>>();
    colsum_kernel<<<dim3(L_ / 256, L_ / 256, HEADS_), 256>>>();

    ctxmean_kernel<<<HEADS_, 256>>>();

    pooled_kernel<<<512, 256>>>(Wo, bo, out);
    weights_kernel<<<(B_ * L_ + 255) / 256, 256>>>(out);
}

// round 2
// speedup vs baseline: 3.5419x; 3.5419x over previous
#include <cuda_runtime.h>
#include <cuda_bf16.h>
#include <cstdint>

#define B_  4
#define L_  2048
#define H_  1024
#define NH_ 16
#define DK_ 64
#define ROWS_ (B_ * L_)          // 8192
#define HEADS_ (B_ * NH_)        // 64
#define NROWS_ (HEADS_ * L_)     // 131072

typedef __nv_bfloat16 bf16;

// ---- scratch (device globals; allocation-free rule) ----
__device__ bf16  g_Xhi[ROWS_ * H_];
__device__ bf16  g_Xlo[ROWS_ * H_];
__device__ bf16  g_Wqh[H_ * H_];
__device__ bf16  g_Wkh[H_ * H_];
__device__ bf16  g_Wvh[H_ * H_];
__device__ bf16  g_Wvl[H_ * H_];
__device__ bf16  g_Qh[HEADS_ * L_ * DK_];       // (head, l, dk) bf16, scaled 1/8
__device__ bf16  g_Kh[HEADS_ * L_ * DK_];
__device__ float g_V [HEADS_ * L_ * DK_];       // fp32
__device__ bf16  g_E [(size_t)HEADS_ * L_ * L_]; // exp(scores), 512MB
__device__ float g_rowsum[NROWS_];
__device__ float g_linv[NROWS_];
__device__ float g_cs[HEADS_ * L_];
__device__ float g_ctxmean[B_ * H_];

// ---------------------------------------------------------------------------
// PTX helpers
// ---------------------------------------------------------------------------
__device__ __forceinline__ uint32_t smem_u32(const void* p) {
    return (uint32_t)__cvta_generic_to_shared(p);
}
__device__ __forceinline__ void ldsm_x4(uint32_t& r0, uint32_t& r1, uint32_t& r2,
                                        uint32_t& r3, uint32_t a) {
    asm volatile("ldmatrix.sync.aligned.m8n8.x4.shared.b16 {%0,%1,%2,%3}, [%4];"
                 : "=r"(r0), "=r"(r1), "=r"(r2), "=r"(r3) : "r"(a));
}
__device__ __forceinline__ void ldsm_x2(uint32_t& r0, uint32_t& r1, uint32_t a) {
    asm volatile("ldmatrix.sync.aligned.m8n8.x2.shared.b16 {%0,%1}, [%2];"
                 : "=r"(r0), "=r"(r1) : "r"(a));
}
__device__ __forceinline__ void mma_bf16(float* c, const uint32_t* a, const uint32_t* b) {
    asm volatile("mma.sync.aligned.m16n8k16.row.col.f32.bf16.bf16.f32 "
                 "{%0,%1,%2,%3}, {%4,%5,%6,%7}, {%8,%9}, {%0,%1,%2,%3};"
                 : "+f"(c[0]), "+f"(c[1]), "+f"(c[2]), "+f"(c[3])
                 : "r"(a[0]), "r"(a[1]), "r"(a[2]), "r"(a[3]), "r"(b[0]), "r"(b[1]));
}
__device__ __forceinline__ void cp16(uint32_t dst, const void* src) {
    asm volatile("cp.async.cg.shared.global [%0], [%1], 16;" :: "r"(dst), "l"(src));
}

// ---------------------------------------------------------------------------
// split fp32 -> bf16 hi (+ optional lo residual)
// ---------------------------------------------------------------------------
__global__ void split_k(const float* __restrict__ in, bf16* __restrict__ hi,
                        bf16* __restrict__ lo, int n)
{
    int i = blockIdx.x * blockDim.x + threadIdx.x;
    if (i >= n) return;
    float v = in[i];
    bf16 h = __float2bfloat16(v);
    hi[i] = h;
    if (lo) lo[i] = __float2bfloat16(v - __bfloat162float(h));
}

// ---------------------------------------------------------------------------
// zero rowsum + cs (both 131072)
// ---------------------------------------------------------------------------
__global__ void zero_k()
{
    int i = blockIdx.x * blockDim.x + threadIdx.x;
    if (i < NROWS_) g_rowsum[i] = 0.f;
    if (i < HEADS_ * L_) g_cs[i] = 0.f;
}

// ---------------------------------------------------------------------------
// GEMM: Y[8192,1024] = A[8192,1024] @ W^T[1024,1024] (+bias)*alpha
// bf16 mma m16n8k16. BM=BN=128, BK=16, 256 thr, warp grid 2x4, warp tile 64x32.
// NPROD: 1 -> hi*hi only; 3 -> hi*hi + hi*lo + lo*hi.
// MODE: 0 -> fp32 out (head layout), 1 -> bf16 out (head layout).
// ---------------------------------------------------------------------------
template<int NPROD, int MODE>
__global__ __launch_bounds__(256)
void gemm_mma(const bf16* __restrict__ Ah, const bf16* __restrict__ Al,
              const bf16* __restrict__ Bh, const bf16* __restrict__ Bl,
              const float* __restrict__ bias, float alpha,
              float* __restrict__ outF, bf16* __restrict__ outB)
{
    __shared__ bf16 sAh[2][128][24];
    __shared__ bf16 sBh[2][128][24];
    __shared__ bf16 sAl[2][128][24];
    __shared__ bf16 sBl[2][128][24];

    const int tid = threadIdx.x;
    const int warp = tid >> 5, lane = tid & 31;
    const int wm = warp >> 2, wn = warp & 3;
    const int mbase = wm * 64, nbase = wn * 32;
    const int rowB = blockIdx.y * 128;
    const int colB = blockIdx.x * 128;

    float acc[4][4][4];
#pragma unroll
    for (int i = 0; i < 4; i++)
#pragma unroll
        for (int j = 0; j < 4; j++)
#pragma unroll
            for (int p = 0; p < 4; p++) acc[i][j][p] = 0.f;

    const int lrow = tid >> 1;
    const int lcb  = (tid & 1) * 8;

    auto load_stage = [&](int s, int k0) {
        cp16(smem_u32(&sAh[s][lrow][lcb]), Ah + (size_t)(rowB + lrow) * H_ + k0 + lcb);
        cp16(smem_u32(&sBh[s][lrow][lcb]), Bh + (size_t)(colB + lrow) * H_ + k0 + lcb);
        if (NPROD == 3) {
            cp16(smem_u32(&sAl[s][lrow][lcb]), Al + (size_t)(rowB + lrow) * H_ + k0 + lcb);
            cp16(smem_u32(&sBl[s][lrow][lcb]), Bl + (size_t)(colB + lrow) * H_ + k0 + lcb);
        }
    };

    load_stage(0, 0);
    asm volatile("cp.async.commit_group;");

    const int T = H_ / 16;   // 64
    for (int t = 0; t < T; t++) {
        if (t + 1 < T) {
            load_stage((t + 1) & 1, (t + 1) * 16);
            asm volatile("cp.async.commit_group;");
            asm volatile("cp.async.wait_group 1;");
        } else {
            asm volatile("cp.async.wait_group 0;");
        }
        __syncthreads();
        const int s = t & 1;

        uint32_t ah[4][4], al[4][4], bh[4][2], bl[4][2];
#pragma unroll
        for (int i = 0; i < 4; i++) {
            ldsm_x4(ah[i][0], ah[i][1], ah[i][2], ah[i][3],
                    smem_u32(&sAh[s][mbase + i * 16 + (lane & 15)][(lane >> 4) * 8]));
            if (NPROD == 3)
                ldsm_x4(al[i][0], al[i][1], al[i][2], al[i][3],
                        smem_u32(&sAl[s][mbase + i * 16 + (lane & 15)][(lane >> 4) * 8]));
        }
#pragma unroll
        for (int j = 0; j < 4; j++) {
            ldsm_x2(bh[j][0], bh[j][1],
                    smem_u32(&sBh[s][nbase + j * 8 + (lane & 7)][((lane >> 3) & 1) * 8]));
            if (NPROD == 3)
                ldsm_x2(bl[j][0], bl[j][1],
                        smem_u32(&sBl[s][nbase + j * 8 + (lane & 7)][((lane >> 3) & 1) * 8]));
        }
#pragma unroll
        for (int i = 0; i < 4; i++)
#pragma unroll
            for (int j = 0; j < 4; j++) {
                mma_bf16(acc[i][j], ah[i], bh[j]);
                if (NPROD == 3) {
                    mma_bf16(acc[i][j], ah[i], bl[j]);
                    mma_bf16(acc[i][j], al[i], bh[j]);
                }
            }
        __syncthreads();
    }

    // epilogue: write head-major layout
    const int group = lane >> 2, qd = lane & 3;
#pragma unroll
    for (int i = 0; i < 4; i++) {
        const int r0 = rowB + mbase + i * 16 + group;
#pragma unroll
        for (int j = 0; j < 4; j++) {
            const int c = colB + nbase + j * 8 + qd * 2;
            const float b0 = bias[c], b1 = bias[c + 1];
            const int nh = c >> 6, dk = c & 63;
#pragma unroll
            for (int half = 0; half < 2; half++) {
                const int r = r0 + half * 8;
                const float v0 = (acc[i][j][half * 2 + 0] + b0) * alpha;
                const float v1 = (acc[i][j][half * 2 + 1] + b1) * alpha;
                const int bb = r >> 11;
                const int l  = r & (L_ - 1);
                const size_t o = ((size_t)((bb * NH_ + nh) * L_ + l)) * DK_ + dk;
                if (MODE == 0) {
                    *(float2*)&outF[o] = make_float2(v0, v1);
                } else {
                    __nv_bfloat162 p;
                    p.x = __float2bfloat16(v0);
                    p.y = __float2bfloat16(v1);
                    *(__nv_bfloat162*)&outB[o] = p;
                }
            }
        }
    }
}

// ---------------------------------------------------------------------------
// Scores: per head, E = exp(Q @ K^T) (Q pre-scaled by 1/8), store bf16,
// accumulate row sums atomically. 128x128 tile per CTA, K=64 in one shot.
// grid (16, 16, 64)
// ---------------------------------------------------------------------------
__global__ __launch_bounds__(256)
void scores_mma()
{
    __shared__ bf16 sQ[128][72];
    __shared__ bf16 sK[128][72];

    const int tid = threadIdx.x;
    const int head = blockIdx.z;
    const int qB = blockIdx.y * 128, kB = blockIdx.x * 128;
    const bf16* Qp = g_Qh + (size_t)head * L_ * DK_;
    const bf16* Kp = g_Kh + (size_t)head * L_ * DK_;

#pragma unroll
    for (int it = 0; it < 4; it++) {
        int idx = tid + it * 256;
        int row = idx >> 3, col = (idx & 7) * 8;
        *(uint4*)&sQ[row][col] = *(const uint4*)&Qp[(size_t)(qB + row) * DK_ + col];
        *(uint4*)&sK[row][col] = *(const uint4*)&Kp[(size_t)(kB + row) * DK_ + col];
    }
    __syncthreads();

    const int warp = tid >> 5, lane = tid & 31;
    const int wm = warp >> 2, wn = warp & 3;
    const int mbase = wm * 64, nbase = wn * 32;

    float acc[4][4][4];
#pragma unroll
    for (int i = 0; i < 4; i++)
#pragma unroll
        for (int j = 0; j < 4; j++)
#pragma unroll
            for (int p = 0; p < 4; p++) acc[i][j][p] = 0.f;

#pragma unroll
    for (int kk = 0; kk < 64; kk += 16) {
        uint32_t ah[4][4], bh[4][2];
#pragma unroll
        for (int i = 0; i < 4; i++)
            ldsm_x4(ah[i][0], ah[i][1], ah[i][2], ah[i][3],
                    smem_u32(&sQ[mbase + i * 16 + (lane & 15)][kk + (lane >> 4) * 8]));
#pragma unroll
        for (int j = 0; j < 4; j++)
            ldsm_x2(bh[j][0], bh[j][1],
                    smem_u32(&sK[nbase + j * 8 + (lane & 7)][kk + ((lane >> 3) & 1) * 8]));
#pragma unroll
        for (int i = 0; i < 4; i++)
#pragma unroll
            for (int j = 0; j < 4; j++)
                mma_bf16(acc[i][j], ah[i], bh[j]);
    }

    // epilogue: exp, store bf16, row-sum partials -> atomics
    const int group = lane >> 2, qd = lane & 3;
    bf16* Ep = g_E + (size_t)head * L_ * L_;
#pragma unroll
    for (int i = 0; i < 4; i++) {
        float rs0 = 0.f, rs1 = 0.f;
#pragma unroll
        for (int j = 0; j < 4; j++) {
            const int c = kB + nbase + j * 8 + qd * 2;
#pragma unroll
            for (int half = 0; half < 2; half++) {
                const float e0 = __expf(acc[i][j][half * 2 + 0]);
                const float e1 = __expf(acc[i][j][half * 2 + 1]);
                if (half == 0) rs0 += e0 + e1; else rs1 += e0 + e1;
                __nv_bfloat162 p;
                p.x = __float2bfloat16(e0);
                p.y = __float2bfloat16(e1);
                const int r = qB + mbase + i * 16 + group + half * 8;
                *(__nv_bfloat162*)&Ep[(size_t)r * L_ + c] = p;
            }
        }
        rs0 += __shfl_xor_sync(0xFFFFFFFFu, rs0, 1);
        rs0 += __shfl_xor_sync(0xFFFFFFFFu, rs0, 2);
        rs1 += __shfl_xor_sync(0xFFFFFFFFu, rs1, 1);
        rs1 += __shfl_xor_sync(0xFFFFFFFFu, rs1, 2);
        if ((lane & 3) == 0) {
            const int rr = head * L_ + qB + mbase + i * 16 + group;
            atomicAdd(&g_rowsum[rr], rs0);
            atomicAdd(&g_rowsum[rr + 8], rs1);
        }
    }
}

// ---------------------------------------------------------------------------
__global__ void recip_k()
{
    int i = blockIdx.x * blockDim.x + threadIdx.x;
    if (i < NROWS_) g_linv[i] = 1.f / g_rowsum[i];
}

// ---------------------------------------------------------------------------
// Column sums of attn: cs[head][k] += sum_q E[q][k] * linv[q]
// grid (8 kchunks of 256, 4 qchunks of 512, 64 heads)
// ---------------------------------------------------------------------------
__global__ __launch_bounds__(256)
void colsum_mma()
{
    const int col  = blockIdx.x * 256 + threadIdx.x;
    const int q0   = blockIdx.y * 512;
    const int head = blockIdx.z;

    const bf16* Ep = g_E + (size_t)head * L_ * L_;
    const float* lp = g_linv + head * L_;

    float acc = 0.f;
#pragma unroll 4
    for (int q = q0; q < q0 + 512; q++)
        acc += __bfloat162float(Ep[(size_t)q * L_ + col]) * lp[q];
    atomicAdd(&g_cs[head * L_ + col], acc);
}

// ---------------------------------------------------------------------------
// ctxmean[b, nh*64+dk] = (1/L) * sum_k cs[head,k] * V[head,k,dk]
// ---------------------------------------------------------------------------
__global__ __launch_bounds__(256)
void ctxmean_kernel()
{
    __shared__ float sm[4][64];
    const int head = blockIdx.x;
    const int dk = threadIdx.x & 63;
    const int ks = threadIdx.x >> 6;

    const float* Vh = g_V + (size_t)head * L_ * DK_;
    const float* cs = g_cs + head * L_;

    float acc = 0.f;
    for (int k = ks; k < L_; k += 4)
        acc += cs[k] * Vh[(size_t)k * DK_ + dk];
    sm[ks][dk] = acc;
    __syncthreads();
    if (threadIdx.x < 64) {
        float t = sm[0][dk] + sm[1][dk] + sm[2][dk] + sm[3][dk];
        int b  = head >> 4;
        int nh = head & 15;
        g_ctxmean[b * H_ + nh * DK_ + dk] = t * (1.f / (float)L_);
    }
}

// ---------------------------------------------------------------------------
// pooled[b,o] = ctxmean[b,:] . Wo[o,:] + bo[o]
// ---------------------------------------------------------------------------
__global__ __launch_bounds__(256)
void pooled_kernel(const float* __restrict__ Wo, const float* __restrict__ bo,
                   float* __restrict__ out)
{
    const int warp = threadIdx.x >> 5;
    const int lane = threadIdx.x & 31;
    const int idx = blockIdx.x * 8 + warp;
    const int b = idx >> 10;
    const int o = idx & 1023;

    const float* cm = g_ctxmean + b * H_;
    const float* wr = Wo + (size_t)o * H_;
    float acc = 0.f;
#pragma unroll
    for (int h = lane; h < H_; h += 32) acc += cm[h] * wr[h];
#pragma unroll
    for (int off = 16; off > 0; off >>= 1)
        acc += __shfl_xor_sync(0xFFFFFFFFu, acc, off);
    if (lane == 0) out[idx] = acc + bo[o];
}

// ---------------------------------------------------------------------------
// weights[b,k] = (1/(NH*L)) sum_nh cs[(b*16+nh), k]
// ---------------------------------------------------------------------------
__global__ void weights_kernel(float* __restrict__ out)
{
    int i = blockIdx.x * blockDim.x + threadIdx.x;
    if (i >= B_ * L_) return;
    int b = i >> 11;
    int k = i & (L_ - 1);
    float s = 0.f;
#pragma unroll
    for (int nh = 0; nh < NH_; nh++)
        s += g_cs[(b * NH_ + nh) * L_ + k];
    out[B_ * H_ + i] = s * (1.f / (float)(NH_ * L_));
}

// ---------------------------------------------------------------------------
extern "C" void kernel_launch(void* const* d_in, const int* in_sizes, int n_in,
                              void* d_out, int out_size)
{
    const float* x  = (const float*)d_in[0];
    const float* Wq = (const float*)d_in[1];
    const float* bq = (const float*)d_in[2];
    const float* Wk = (const float*)d_in[3];
    const float* bk = (const float*)d_in[4];
    const float* Wv = (const float*)d_in[5];
    const float* bv = (const float*)d_in[6];
    const float* Wo = (const float*)d_in[7];
    const float* bo = (const float*)d_in[8];
    float* out = (float*)d_out;

    bf16 *dXhi, *dXlo, *dWqh, *dWkh, *dWvh, *dWvl, *dQh, *dKh;
    float *dV;
    cudaGetSymbolAddress((void**)&dXhi, g_Xhi);
    cudaGetSymbolAddress((void**)&dXlo, g_Xlo);
    cudaGetSymbolAddress((void**)&dWqh, g_Wqh);
    cudaGetSymbolAddress((void**)&dWkh, g_Wkh);
    cudaGetSymbolAddress((void**)&dWvh, g_Wvh);
    cudaGetSymbolAddress((void**)&dWvl, g_Wvl);
    cudaGetSymbolAddress((void**)&dQh,  g_Qh);
    cudaGetSymbolAddress((void**)&dKh,  g_Kh);
    cudaGetSymbolAddress((void**)&dV,   g_V);

    split_k<<<(ROWS_ * H_) / 256, 256>>>(x,  dXhi, dXlo, ROWS_ * H_);
    split_k<<<(H_ * H_) / 256, 256>>>(Wq, dWqh, nullptr, H_ * H_);
    split_k<<<(H_ * H_) / 256, 256>>>(Wk, dWkh, nullptr, H_ * H_);
    split_k<<<(H_ * H_) / 256, 256>>>(Wv, dWvh, dWvl,   H_ * H_);
    zero_k<<<NROWS_ / 256, 256>>>();

    dim3 gg(H_ / 128, ROWS_ / 128);  // (8, 64)
    gemm_mma<1, 1><<<gg, 256>>>(dXhi, nullptr, dWqh, nullptr, bq, 0.125f, nullptr, dQh);
    gemm_mma<1, 1><<<gg, 256>>>(dXhi, nullptr, dWkh, nullptr, bk, 1.0f,   nullptr, dKh);
    gemm_mma<3, 0><<<gg, 256>>>(dXhi, dXlo,    dWvh, dWvl,    bv, 1.0f,   dV, nullptr);

    scores_mma<<<dim3(L_ / 128, L_ / 128, HEADS_), 256>>>();
    recip_k<<<NROWS_ / 256, 256>>>();
    colsum_mma<<<dim3(L_ / 256, L_ / 512, HEADS_), 256>>>();

    ctxmean_kernel<<<HEADS_, 256>>>();
    pooled_kernel<<<512, 256>>>(Wo, bo, out);
    weights_kernel<<<(B_ * L_ + 255) / 256, 256>>>(out);
}

// round 4
// speedup vs baseline: 5.4032x; 1.5255x over previous
#include <cuda_runtime.h>
#include <cuda_bf16.h>
#include <cstdint>

#define B_  4
#define L_  2048
#define H_  1024
#define NH_ 16
#define DK_ 64
#define ROWS_ (B_ * L_)          // 8192
#define HEADS_ (B_ * NH_)        // 64

typedef __nv_bfloat16 bf16;

// ---- scratch (device globals; allocation-free rule) ----
__device__ bf16  g_Xhi[ROWS_ * H_];
__device__ bf16  g_Wqh[H_ * H_];
__device__ bf16  g_Wkh[H_ * H_];
__device__ bf16  g_Qb[ROWS_ * H_];    // row-major (b*L+l, h), Q pre-scaled 1/8
__device__ bf16  g_Kb[ROWS_ * H_];
__device__ float g_cs[HEADS_ * L_];   // per-head attn column sums
__device__ float g_wsum[HEADS_ * H_]; // (1/L) cs_head @ x_b
__device__ float g_ctxmean[B_ * H_];

// ---------------------------------------------------------------------------
// PTX helpers
// ---------------------------------------------------------------------------
__device__ __forceinline__ uint32_t smem_u32(const void* p) {
    return (uint32_t)__cvta_generic_to_shared(p);
}
__device__ __forceinline__ void ldsm_x4(uint32_t& r0, uint32_t& r1, uint32_t& r2,
                                        uint32_t& r3, uint32_t a) {
    asm volatile("ldmatrix.sync.aligned.m8n8.x4.shared.b16 {%0,%1,%2,%3}, [%4];"
                 : "=r"(r0), "=r"(r1), "=r"(r2), "=r"(r3) : "r"(a));
}
__device__ __forceinline__ void ldsm_x2(uint32_t& r0, uint32_t& r1, uint32_t a) {
    asm volatile("ldmatrix.sync.aligned.m8n8.x2.shared.b16 {%0,%1}, [%2];"
                 : "=r"(r0), "=r"(r1) : "r"(a));
}
__device__ __forceinline__ void mma_bf16(float* c, const uint32_t* a, const uint32_t* b) {
    asm volatile("mma.sync.aligned.m16n8k16.row.col.f32.bf16.bf16.f32 "
                 "{%0,%1,%2,%3}, {%4,%5,%6,%7}, {%8,%9}, {%0,%1,%2,%3};"
                 : "+f"(c[0]), "+f"(c[1]), "+f"(c[2]), "+f"(c[3])
                 : "r"(a[0]), "r"(a[1]), "r"(a[2]), "r"(a[3]), "r"(b[0]), "r"(b[1]));
}
__device__ __forceinline__ void cp16(uint32_t dst, const void* src) {
    asm volatile("cp.async.cg.shared.global [%0], [%1], 16;" :: "r"(dst), "l"(src));
}
#define CP_COMMIT()  asm volatile("cp.async.commit_group;" ::: "memory")
#define CP_WAIT0()   asm volatile("cp.async.wait_group 0;" ::: "memory")

// ---------------------------------------------------------------------------
// split fp32 -> bf16
// ---------------------------------------------------------------------------
__global__ void split_k(const float* __restrict__ in, bf16* __restrict__ hi, int n)
{
    int i = blockIdx.x * blockDim.x + threadIdx.x;
    if (i >= n) return;
    hi[i] = __float2bfloat16(in[i]);
}

// ---------------------------------------------------------------------------
__global__ void zero_k()
{
    int i = blockIdx.x * blockDim.x + threadIdx.x;
    if (i < HEADS_ * L_) g_cs[i] = 0.f;
    if (i < HEADS_ * H_) g_wsum[i] = 0.f;
}

// ---------------------------------------------------------------------------
// GEMM: Y[8192,1024] = A @ W^T (+bias)*alpha, bf16 out row-major.
// bf16 mma m16n8k16. BM=BN=128, BK=16, 256 thr, warp 64x32 tiles.
// ---------------------------------------------------------------------------
__global__ __launch_bounds__(256)
void gemm_rm(const bf16* __restrict__ Ah, const bf16* __restrict__ Bh,
             const float* __restrict__ bias, float alpha, bf16* __restrict__ outB)
{
    __shared__ bf16 sAh[2][128][24];
    __shared__ bf16 sBh[2][128][24];

    const int tid = threadIdx.x;
    const int warp = tid >> 5, lane = tid & 31;
    const int wm = warp >> 2, wn = warp & 3;
    const int mbase = wm * 64, nbase = wn * 32;
    const int rowB = blockIdx.y * 128;
    const int colB = blockIdx.x * 128;

    float acc[4][4][4];
#pragma unroll
    for (int i = 0; i < 4; i++)
#pragma unroll
        for (int j = 0; j < 4; j++)
#pragma unroll
            for (int p = 0; p < 4; p++) acc[i][j][p] = 0.f;

    const int lrow = tid >> 1;
    const int lcb  = (tid & 1) * 8;

    auto load_stage = [&](int s, int k0) {
        cp16(smem_u32(&sAh[s][lrow][lcb]), Ah + (size_t)(rowB + lrow) * H_ + k0 + lcb);
        cp16(smem_u32(&sBh[s][lrow][lcb]), Bh + (size_t)(colB + lrow) * H_ + k0 + lcb);
    };

    load_stage(0, 0);
    CP_COMMIT();

    const int T = H_ / 16;   // 64
    for (int t = 0; t < T; t++) {
        if (t + 1 < T) {
            load_stage((t + 1) & 1, (t + 1) * 16);
            CP_COMMIT();
            asm volatile("cp.async.wait_group 1;" ::: "memory");
        } else {
            CP_WAIT0();
        }
        __syncthreads();
        const int s = t & 1;

        uint32_t ah[4][4], bh[4][2];
#pragma unroll
        for (int i = 0; i < 4; i++)
            ldsm_x4(ah[i][0], ah[i][1], ah[i][2], ah[i][3],
                    smem_u32(&sAh[s][mbase + i * 16 + (lane & 15)][(lane >> 4) * 8]));
#pragma unroll
        for (int j = 0; j < 4; j++)
            ldsm_x2(bh[j][0], bh[j][1],
                    smem_u32(&sBh[s][nbase + j * 8 + (lane & 7)][((lane >> 3) & 1) * 8]));
#pragma unroll
        for (int i = 0; i < 4; i++)
#pragma unroll
            for (int j = 0; j < 4; j++)
                mma_bf16(acc[i][j], ah[i], bh[j]);
        __syncthreads();
    }

    // epilogue: row-major bf16
    const int group = lane >> 2, qd = lane & 3;
#pragma unroll
    for (int i = 0; i < 4; i++) {
        const int r0 = rowB + mbase + i * 16 + group;
#pragma unroll
        for (int j = 0; j < 4; j++) {
            const int c = colB + nbase + j * 8 + qd * 2;
            const float b0 = bias[c], b1 = bias[c + 1];
#pragma unroll
            for (int half = 0; half < 2; half++) {
                const int r = r0 + half * 8;
                __nv_bfloat162 p;
                p.x = __float2bfloat16((acc[i][j][half * 2 + 0] + b0) * alpha);
                p.y = __float2bfloat16((acc[i][j][half * 2 + 1] + b1) * alpha);
                *(__nv_bfloat162*)&outB[(size_t)r * H_ + c] = p;
            }
        }
    }
}

// ---------------------------------------------------------------------------
// Fused scores: per (q-tile 128, head). Two passes over 16 K-tiles:
//  pass 1: S = Q K^T, exp, exact row sums (registers)
//  pass 2: recompute S, exp * (1/rowsum), column-reduce -> smem cs -> global
// grid (16, 64), 256 threads. Dynamic smem 66048 B.
// ---------------------------------------------------------------------------
#define SQ_PITCH 72
__global__ __launch_bounds__(256)
void scores_fused()
{
    extern __shared__ __align__(16) char dsm[];
    bf16*  sQ   = (bf16*)dsm;                              // 128*72*2  = 18432
    bf16*  sK0  = (bf16*)(dsm + 18432);                    // 18432
    bf16*  sK1  = (bf16*)(dsm + 36864);                    // 18432
    float* rs   = (float*)(dsm + 55296);                   // 128*4*4   = 2048
    float* linv = (float*)(dsm + 57344);                   // 512
    float* csp  = (float*)(dsm + 57856);                   // 2048*4    = 8192

    const int tid = threadIdx.x;
    const int warp = tid >> 5, lane = tid & 31;
    const int wm = warp >> 2, wn = warp & 3;
    const int mbase = wm * 64, nbase = wn * 32;
    const int group = lane >> 2, qd = lane & 3;
    const int head = blockIdx.y;
    const int b = head >> 4, nh = head & 15;
    const int qB = blockIdx.x * 128;

    // load Q tile (128 x 64) once
#pragma unroll
    for (int it = 0; it < 4; it++) {
        int idx = tid + it * 256;
        int row = idx >> 3, col = (idx & 7) * 8;
        *(uint4*)&sQ[row * SQ_PITCH + col] =
            *(const uint4*)&g_Qb[(size_t)(b * L_ + qB + row) * H_ + nh * 64 + col];
    }

    bf16* sK[2] = { sK0, sK1 };
    auto loadK = [&](int s, int kt) {
#pragma unroll
        for (int it = 0; it < 4; it++) {
            int idx = tid + it * 256;
            int row = idx >> 3, col = (idx & 7) * 8;
            cp16(smem_u32(&sK[s][row * SQ_PITCH + col]),
                 &g_Kb[(size_t)(b * L_ + kt * 128 + row) * H_ + nh * 64 + col]);
        }
        CP_COMMIT();
    };

    float racc[4][2];
#pragma unroll
    for (int i = 0; i < 4; i++) { racc[i][0] = 0.f; racc[i][1] = 0.f; }

    float acc[4][4][4];
    uint32_t ah[4][4], bh[4][2];

    auto mma_tile = [&](const bf16* kbuf) {
#pragma unroll
        for (int i = 0; i < 4; i++)
#pragma unroll
            for (int j = 0; j < 4; j++)
#pragma unroll
                for (int p = 0; p < 4; p++) acc[i][j][p] = 0.f;
#pragma unroll
        for (int kk = 0; kk < 64; kk += 16) {
#pragma unroll
            for (int i = 0; i < 4; i++)
                ldsm_x4(ah[i][0], ah[i][1], ah[i][2], ah[i][3],
                        smem_u32(&sQ[(mbase + i * 16 + (lane & 15)) * SQ_PITCH +
                                     kk + (lane >> 4) * 8]));
#pragma unroll
            for (int j = 0; j < 4; j++)
                ldsm_x2(bh[j][0], bh[j][1],
                        smem_u32(&kbuf[(nbase + j * 8 + (lane & 7)) * SQ_PITCH +
                                       kk + ((lane >> 3) & 1) * 8]));
#pragma unroll
            for (int i = 0; i < 4; i++)
#pragma unroll
                for (int j = 0; j < 4; j++)
                    mma_bf16(acc[i][j], ah[i], bh[j]);
        }
    };

    // ---------------- pass 1: row sums ----------------
    loadK(0, 0);
    for (int kt = 0; kt < 16; kt++) {
        CP_WAIT0();
        __syncthreads();
        if (kt + 1 < 16) loadK((kt + 1) & 1, kt + 1);
        mma_tile(sK[kt & 1]);
#pragma unroll
        for (int i = 0; i < 4; i++)
#pragma unroll
            for (int j = 0; j < 4; j++) {
                racc[i][0] += __expf(acc[i][j][0]) + __expf(acc[i][j][1]);
                racc[i][1] += __expf(acc[i][j][2]) + __expf(acc[i][j][3]);
            }
    }
    // reduce over qd lanes, store per-wn partials
#pragma unroll
    for (int i = 0; i < 4; i++)
#pragma unroll
        for (int h = 0; h < 2; h++) {
            racc[i][h] += __shfl_xor_sync(0xFFFFFFFFu, racc[i][h], 1);
            racc[i][h] += __shfl_xor_sync(0xFFFFFFFFu, racc[i][h], 2);
        }
    if (qd == 0) {
#pragma unroll
        for (int i = 0; i < 4; i++)
#pragma unroll
            for (int h = 0; h < 2; h++)
                rs[(mbase + i * 16 + group + h * 8) * 4 + wn] = racc[i][h];
    }
    __syncthreads();
    if (tid < 128)
        linv[tid] = 1.f / (rs[tid * 4] + rs[tid * 4 + 1] + rs[tid * 4 + 2] + rs[tid * 4 + 3]);
#pragma unroll
    for (int t = 0; t < 8; t++) csp[tid + t * 256] = 0.f;
    __syncthreads();

    // per-thread row inverse factors (constant across pass 2)
    float li[4][2];
#pragma unroll
    for (int i = 0; i < 4; i++)
#pragma unroll
        for (int h = 0; h < 2; h++)
            li[i][h] = linv[mbase + i * 16 + group + h * 8];

    // ---------------- pass 2: column sums ----------------
    loadK(0, 0);
    for (int kt = 0; kt < 16; kt++) {
        CP_WAIT0();
        __syncthreads();
        if (kt + 1 < 16) loadK((kt + 1) & 1, kt + 1);
        mma_tile(sK[kt & 1]);

        float colacc[8];
#pragma unroll
        for (int m = 0; m < 8; m++) colacc[m] = 0.f;
#pragma unroll
        for (int i = 0; i < 4; i++)
#pragma unroll
            for (int j = 0; j < 4; j++) {
                colacc[2 * j + 0] += __expf(acc[i][j][0]) * li[i][0]
                                   + __expf(acc[i][j][2]) * li[i][1];
                colacc[2 * j + 1] += __expf(acc[i][j][1]) * li[i][0]
                                   + __expf(acc[i][j][3]) * li[i][1];
            }
#pragma unroll
        for (int m = 0; m < 8; m++) {
            colacc[m] += __shfl_xor_sync(0xFFFFFFFFu, colacc[m], 4);
            colacc[m] += __shfl_xor_sync(0xFFFFFFFFu, colacc[m], 8);
            colacc[m] += __shfl_xor_sync(0xFFFFFFFFu, colacc[m], 16);
        }
        if (lane < 4) {
#pragma unroll
            for (int j = 0; j < 4; j++) {
                atomicAdd(&csp[kt * 128 + nbase + j * 8 + lane * 2 + 0], colacc[2 * j + 0]);
                atomicAdd(&csp[kt * 128 + nbase + j * 8 + lane * 2 + 1], colacc[2 * j + 1]);
            }
        }
    }
    __syncthreads();
#pragma unroll
    for (int t = 0; t < 8; t++)
        atomicAdd(&g_cs[head * L_ + tid + t * 256], csp[tid + t * 256]);
}

// ---------------------------------------------------------------------------
// wsum[head][h] = (1/L) sum_k cs[head,k] * x[b*L+k, h]   (fp32 exact)
// grid (8 hchunks, 4 b, 4 kchunks), 128 threads
// ---------------------------------------------------------------------------
__global__ __launch_bounds__(128)
void wsum_k(const float* __restrict__ x)
{
    __shared__ float scs[16][512];
    const int tid = threadIdx.x;
    const int h  = blockIdx.x * 128 + tid;
    const int b  = blockIdx.y;
    const int k0 = blockIdx.z * 512;

#pragma unroll
    for (int it = 0; it < 64; it++) {
        int w = tid + it * 128;
        scs[w >> 9][w & 511] = g_cs[(b * NH_ + (w >> 9)) * L_ + k0 + (w & 511)];
    }
    __syncthreads();

    float acc[16];
#pragma unroll
    for (int nh = 0; nh < NH_; nh++) acc[nh] = 0.f;

    const float* xp = x + (size_t)(b * L_ + k0) * H_ + h;
#pragma unroll 4
    for (int kk = 0; kk < 512; kk++) {
        float xv = xp[(size_t)kk * H_];
#pragma unroll
        for (int nh = 0; nh < NH_; nh++) acc[nh] += scs[nh][kk] * xv;
    }
#pragma unroll
    for (int nh = 0; nh < NH_; nh++)
        atomicAdd(&g_wsum[(b * NH_ + nh) * H_ + h], acc[nh] * (1.f / (float)L_));
}

// ---------------------------------------------------------------------------
// ctxmean[b, nh*64+dk] = sum_h wsum[head,h] * Wv[nh*64+dk, h] + bv[nh*64+dk]
// grid 64 (head), 256 threads (8 warps x 8 dk each)
// ---------------------------------------------------------------------------
__global__ __launch_bounds__(256)
void ctx_k(const float* __restrict__ Wv, const float* __restrict__ bv)
{
    __shared__ float sw[H_];
    const int tid = threadIdx.x;
    const int warp = tid >> 5, lane = tid & 31;
    const int head = blockIdx.x;
    const int b = head >> 4, nh = head & 15;

#pragma unroll
    for (int it = 0; it < 4; it++)
        sw[tid + it * 256] = g_wsum[head * H_ + tid + it * 256];
    __syncthreads();

#pragma unroll
    for (int d = 0; d < 8; d++) {
        const int dk = warp * 8 + d;
        const float* wr = Wv + (size_t)(nh * 64 + dk) * H_;
        float acc = 0.f;
#pragma unroll 8
        for (int h = lane; h < H_; h += 32) acc += sw[h] * wr[h];
#pragma unroll
        for (int off = 16; off > 0; off >>= 1)
            acc += __shfl_xor_sync(0xFFFFFFFFu, acc, off);
        if (lane == 0)
            g_ctxmean[b * H_ + nh * 64 + dk] = acc + bv[nh * 64 + dk];
    }
}

// ---------------------------------------------------------------------------
__global__ __launch_bounds__(256)
void pooled_kernel(const float* __restrict__ Wo, const float* __restrict__ bo,
                   float* __restrict__ out)
{
    const int warp = threadIdx.x >> 5;
    const int lane = threadIdx.x & 31;
    const int idx = blockIdx.x * 8 + warp;
    const int b = idx >> 10;
    const int o = idx & 1023;

    const float* cm = g_ctxmean + b * H_;
    const float* wr = Wo + (size_t)o * H_;
    float acc = 0.f;
#pragma unroll
    for (int h = lane; h < H_; h += 32) acc += cm[h] * wr[h];
#pragma unroll
    for (int off = 16; off > 0; off >>= 1)
        acc += __shfl_xor_sync(0xFFFFFFFFu, acc, off);
    if (lane == 0) out[idx] = acc + bo[o];
}

// ---------------------------------------------------------------------------
__global__ void weights_kernel(float* __restrict__ out)
{
    int i = blockIdx.x * blockDim.x + threadIdx.x;
    if (i >= B_ * L_) return;
    int b = i >> 11;
    int k = i & (L_ - 1);
    float s = 0.f;
#pragma unroll
    for (int nh = 0; nh < NH_; nh++)
        s += g_cs[(b * NH_ + nh) * L_ + k];
    out[B_ * H_ + i] = s * (1.f / (float)(NH_ * L_));
}

// ---------------------------------------------------------------------------
extern "C" void kernel_launch(void* const* d_in, const int* in_sizes, int n_in,
                              void* d_out, int out_size)
{
    const float* x  = (const float*)d_in[0];
    const float* Wq = (const float*)d_in[1];
    const float* bq = (const float*)d_in[2];
    const float* Wk = (const float*)d_in[3];
    const float* bk = (const float*)d_in[4];
    const float* Wv = (const float*)d_in[5];
    const float* bv = (const float*)d_in[6];
    const float* Wo = (const float*)d_in[7];
    const float* bo = (const float*)d_in[8];
    float* out = (float*)d_out;

    bf16 *dXhi, *dWqh, *dWkh, *dQb, *dKb;
    cudaGetSymbolAddress((void**)&dXhi, g_Xhi);
    cudaGetSymbolAddress((void**)&dWqh, g_Wqh);
    cudaGetSymbolAddress((void**)&dWkh, g_Wkh);
    cudaGetSymbolAddress((void**)&dQb,  g_Qb);
    cudaGetSymbolAddress((void**)&dKb,  g_Kb);

    cudaFuncSetAttribute(scores_fused, cudaFuncAttributeMaxDynamicSharedMemorySize, 66048);

    split_k<<<(ROWS_ * H_) / 256, 256>>>(x,  dXhi, ROWS_ * H_);
    split_k<<<(H_ * H_) / 256, 256>>>(Wq, dWqh, H_ * H_);
    split_k<<<(H_ * H_) / 256, 256>>>(Wk, dWkh, H_ * H_);
    zero_k<<<(HEADS_ * L_) / 256, 256>>>();

    dim3 gg(H_ / 128, ROWS_ / 128);   // (8, 64)
    gemm_rm<<<gg, 256>>>(dXhi, dWqh, bq, 0.125f, dQb);
    gemm_rm<<<gg, 256>>>(dXhi, dWkh, bk, 1.0f,   dKb);

    scores_fused<<<dim3(L_ / 128, HEADS_), 256, 66048>>>();

    wsum_k<<<dim3(8, B_, 4), 128>>>(x);
    ctx_k<<<HEADS_, 256>>>(Wv, bv);
    pooled_kernel<<<512, 256>>>(Wo, bo, out);
    weights_kernel<<<(B_ * L_ + 255) / 256, 256>>>(out);
}